// round 15
// baseline (speedup 1.0000x reference)
#include <cuda_runtime.h>
#include <cuda_fp16.h>

#define HDIM   64
#define NHEADS 4
#define QKDIM  256           // NHEADS * HDIM
#define N_SRC  50000
#define N_TGT  10000
#define N_E    250000
#define N_LBL  200000

#define PADK   72            // smem row stride in fp16 (144B): ldmatrix conflict-free
#define WSECT  (832 * 64)    // per (layer,edge_type) transposed weight block (elements)

// ---------------- scratch (static device memory; no allocations) ----------------
__device__ float g_xs_a[N_SRC * HDIM];
__device__ float g_xs_b[N_SRC * HDIM];
__device__ float g_xt_a[N_TGT * HDIM];
__device__ float g_xt_b[N_TGT * HDIM];

// fp16 edge operands
__device__ __align__(16) __half g_q_st[N_TGT * QKDIM];
__device__ __align__(16) __half g_k_ts[N_TGT * QKDIM];
__device__ __align__(16) __half g_v_ts[N_TGT * QKDIM];
__device__ __align__(16) __half g_q_ts[N_SRC * QKDIM];
__device__ __align__(16) __half g_k_st[N_SRC * QKDIM];
__device__ __align__(16) __half g_v_st[N_SRC * QKDIM];

__device__ __align__(16) float g_sc_st[N_E * NHEADS];
__device__ __align__(16) float g_sc_ts[N_E * NHEADS];
__device__ __align__(16) float g_d_st[N_TGT * NHEADS];
__device__ __align__(16) float g_d_ts[N_SRC * NHEADS];

// A operand: fp16. B: split-fp16 (hi + residual).
__device__ __align__(16) __half g_xsh[N_SRC * HDIM];
__device__ __align__(16) __half g_xth[N_TGT * HDIM];
__device__ __align__(16) __half g_wth[4 * WSECT];
__device__ __align__(16) __half g_wtl[4 * WSECT];

// ---------------- helpers ----------------
__device__ __forceinline__ void split2h(float v, __half& h, __half& l) {
    h = __float2half_rn(v);
    l = __float2half_rn(v - __half2float(h));
}
__device__ __forceinline__ unsigned su32(const void* p) {
    unsigned a;
    asm("{ .reg .u64 t; cvta.to.shared.u64 t, %1; cvt.u32.u64 %0, t; }" : "=r"(a) : "l"(p));
    return a;
}
__device__ __forceinline__ void ldsm4(unsigned& r0, unsigned& r1, unsigned& r2, unsigned& r3,
                                      unsigned addr) {
    asm volatile("ldmatrix.sync.aligned.m8n8.x4.shared.b16 {%0,%1,%2,%3}, [%4];"
                 : "=r"(r0), "=r"(r1), "=r"(r2), "=r"(r3) : "r"(addr));
}
__device__ __forceinline__ void mma16816h(float* d, const unsigned* a, unsigned b0, unsigned b1) {
    asm volatile("mma.sync.aligned.m16n8k16.row.col.f32.f16.f16.f32 "
                 "{%0,%1,%2,%3}, {%4,%5,%6,%7}, {%8,%9}, {%0,%1,%2,%3};"
                 : "+f"(d[0]), "+f"(d[1]), "+f"(d[2]), "+f"(d[3])
                 : "r"(a[0]), "r"(a[1]), "r"(a[2]), "r"(a[3]), "r"(b0), "r"(b1));
}
__device__ __forceinline__ float dot8h(uint4 qa, uint4 ka) {
    const __half2* qh = (const __half2*)&qa;
    const __half2* kh = (const __half2*)&ka;
    float dot = 0.0f;
    #pragma unroll
    for (int i = 0; i < 4; i++) {
        float2 a = __half22float2(qh[i]);
        float2 b = __half22float2(kh[i]);
        dot += a.x * b.x + a.y * b.y;
    }
    return dot;
}
// vector reduction add (sm_90+): one 16B atomic instead of 4 scalar ones
__device__ __forceinline__ void red_add_v4(float* p, float a, float b, float c, float d) {
    asm volatile("red.global.add.v4.f32 [%0], {%1, %2, %3, %4};"
                 :: "l"(p), "f"(a), "f"(b), "f"(c), "f"(d) : "memory");
}

// ---------------- small kernels ----------------
__global__ void zero2_kernel(float* __restrict__ a, int na, float* __restrict__ b, int nb) {
    int i = blockIdx.x * blockDim.x + threadIdx.x;
    if (i < na) { a[i] = 0.0f; return; }
    i -= na;
    if (i < nb) b[i] = 0.0f;
}

__global__ void gather_h2(const float* __restrict__ semb, const float* __restrict__ temb,
                          const int* __restrict__ sid, const int* __restrict__ tid) {
    int i = blockIdx.x * blockDim.x + threadIdx.x;
    if (i < N_SRC * HDIM) {
        int row = i >> 6, d = i & 63;
        g_xsh[i] = __float2half_rn(semb[(size_t)sid[row] * HDIM + d]);
    } else if (i < (N_SRC + N_TGT) * HDIM) {
        int j = i - N_SRC * HDIM;
        int row = j >> 6, d = j & 63;
        g_xth[j] = __float2half_rn(temb[(size_t)tid[row] * HDIM + d]);
    }
}

__global__ void relu_h2() {
    int i = blockIdx.x * blockDim.x + threadIdx.x;
    if (i < N_SRC * HDIM) {
        g_xsh[i] = __float2half_rn(fmaxf(g_xs_b[i], 0.0f));
    } else if (i < (N_SRC + N_TGT) * HDIM) {
        int j = i - N_SRC * HDIM;
        g_xth[j] = __float2half_rn(fmaxf(g_xt_b[j], 0.0f));
    }
}

__global__ void split_w(const float* __restrict__ Wq, const float* __restrict__ Wk,
                        const float* __restrict__ Wv, const float* __restrict__ Ws) {
    int i = blockIdx.x * blockDim.x + threadIdx.x;
    if (i >= 4 * WSECT) return;
    int le = i / WSECT, rem = i % WSECT;
    int n = rem >> 6, k = rem & 63;
    float v;
    if (n < 256)      v = Wq[(size_t)le * 64 * 256 + k * 256 + n];
    else if (n < 512) v = Wk[(size_t)le * 64 * 256 + k * 256 + (n - 256)];
    else if (n < 768) v = Wv[(size_t)le * 64 * 256 + k * 256 + (n - 512)];
    else              v = Ws[(size_t)le * 64 * 64 + k * 64 + (n - 768)];
    split2h(v, g_wth[i], g_wtl[i]);
}

// ---------------- tensor-core projection GEMM (R11/R14 champion) ------
__global__ void __launch_bounds__(256) proj_mma(
    const __half* __restrict__ Xh, int N,
    int off0, int off1, int off2, int off3,
    const float* __restrict__ b0, const float* __restrict__ b1,
    const float* __restrict__ b2, const float* __restrict__ b3,
    __half* __restrict__ o0, __half* __restrict__ o1,
    __half* __restrict__ o2, float* __restrict__ o3) {
    extern __shared__ __half sm[];
    __half* Ah = sm;                           // [128][PADK]
    __half* Bh = Ah + 128 * PADK;              // [64][PADK]
    __half* Bl = Bh + 64 * PADK;

    int sec = blockIdx.y;                      // 0..3
    int woff_base, ncb; const float* bias; __half* outh = 0; float* outf = 0;
    if (sec == 0)      { woff_base = off0; bias = b0; outh = o0; ncb = 4; }
    else if (sec == 1) { woff_base = off1; bias = b1; outh = o1; ncb = 4; }
    else if (sec == 2) { woff_base = off2; bias = b2; outh = o2; ncb = 4; }
    else               { woff_base = off3; bias = b3; outf = o3; ncb = 1; }

    int t = threadIdx.x;
    int rowbase = blockIdx.x * 128;

    const uint4* xh4 = (const uint4*)Xh;
    uint4 z4 = make_uint4(0u, 0u, 0u, 0u);
    #pragma unroll
    for (int i = 0; i < 4; i++) {
        int idx = t + i * 256;
        int r = idx >> 3, c = idx & 7;
        int gr = rowbase + r;
        uint4 vh = z4;
        if (gr < N) vh = xh4[(size_t)gr * 8 + c];
        *(uint4*)(Ah + r * PADK + c * 8) = vh;
    }

    int lane = t & 31, warp = t >> 5;
    int wr = warp >> 1, wc = warp & 1;
    int lrow = lane & 7, lsel = lane >> 3;
    unsigned ah_u = su32(Ah), bh_u = su32(Bh), bl_u = su32(Bl);

    for (int lcb = 0; lcb < ncb; lcb++) {
        if (lcb) __syncthreads();
        int woff = woff_base + lcb * 64 * 64;
        const uint4* wh4 = (const uint4*)(g_wth + woff);
        const uint4* wl4 = (const uint4*)(g_wtl + woff);
        #pragma unroll
        for (int i = 0; i < 2; i++) {
            int idx = t + i * 256;
            int n = idx >> 3, c = idx & 7;
            *(uint4*)(Bh + n * PADK + c * 8) = wh4[n * 8 + c];
            *(uint4*)(Bl + n * PADK + c * 8) = wl4[n * 8 + c];
        }
        __syncthreads();

        float acc[2][4][4];
        #pragma unroll
        for (int mt = 0; mt < 2; mt++)
            #pragma unroll
            for (int nt = 0; nt < 4; nt++)
                #pragma unroll
                for (int r = 0; r < 4; r++) acc[mt][nt][r] = 0.0f;

        #pragma unroll
        for (int kc = 0; kc < 4; kc++) {
            int k0 = kc * 16;
            unsigned ah[2][4], bh[2][4], bl[2][4];
            #pragma unroll
            for (int mt = 0; mt < 2; mt++) {
                int row = wr * 32 + mt * 16 + (lsel & 1) * 8 + lrow;
                int koff = k0 + (lsel >> 1) * 8;
                unsigned boff = (unsigned)(row * PADK + koff) * 2u;
                ldsm4(ah[mt][0], ah[mt][1], ah[mt][2], ah[mt][3], ah_u + boff);
            }
            #pragma unroll
            for (int nt2 = 0; nt2 < 2; nt2++) {
                int n = wc * 32 + nt2 * 16 + (lsel >> 1) * 8 + lrow;
                int koff = k0 + (lsel & 1) * 8;
                unsigned boff = (unsigned)(n * PADK + koff) * 2u;
                ldsm4(bh[nt2][0], bh[nt2][1], bh[nt2][2], bh[nt2][3], bh_u + boff);
                ldsm4(bl[nt2][0], bl[nt2][1], bl[nt2][2], bl[nt2][3], bl_u + boff);
            }
            #pragma unroll
            for (int mt = 0; mt < 2; mt++)
                #pragma unroll
                for (int nt = 0; nt < 4; nt++) {
                    int g = nt >> 1, hf = (nt & 1) * 2;
                    mma16816h(acc[mt][nt], ah[mt], bh[g][hf], bh[g][hf + 1]);
                    mma16816h(acc[mt][nt], ah[mt], bl[g][hf], bl[g][hf + 1]);
                }
        }

        #pragma unroll
        for (int mt = 0; mt < 2; mt++) {
            int ra = rowbase + wr * 32 + mt * 16 + (lane >> 2);
            int rb = ra + 8;
            #pragma unroll
            for (int nt = 0; nt < 4; nt++) {
                int col = lcb * 64 + wc * 32 + nt * 8 + (lane & 3) * 2;
                float2 bv = *(const float2*)(bias + col);
                if (sec < 3) {
                    if (ra < N)
                        *(__half2*)(outh + (size_t)ra * 256 + col) =
                            __floats2half2_rn(acc[mt][nt][0] + bv.x, acc[mt][nt][1] + bv.y);
                    if (rb < N)
                        *(__half2*)(outh + (size_t)rb * 256 + col) =
                            __floats2half2_rn(acc[mt][nt][2] + bv.x, acc[mt][nt][3] + bv.y);
                } else {
                    if (ra < N)
                        *(float2*)(outf + (size_t)ra * 64 + col) =
                            make_float2(acc[mt][nt][0] + bv.x, acc[mt][nt][1] + bv.y);
                    if (rb < N)
                        *(float2*)(outf + (size_t)rb * 64 + col) =
                            make_float2(acc[mt][nt][2] + bv.x, acc[mt][nt][3] + bv.y);
                }
            }
        }
    }
}

// ---------------- score+exp+denom: lane-0 v4 store + v4 denom atomic ----------------
__global__ void scoreexp_kernel(const int* __restrict__ esrc, const int* __restrict__ edst,
                                const __half* __restrict__ q, const __half* __restrict__ k,
                                float* __restrict__ score, float* __restrict__ denom,
                                int nedge) {
    int warp = (blockIdx.x * blockDim.x + threadIdx.x) >> 5;
    if (warp >= nedge) return;
    int lane = threadIdx.x & 31;
    int s = esrc[warp], d = edst[warp];
    int h = lane >> 3, sub = lane & 7;
    uint4 qa = *(const uint4*)(q + (size_t)d * QKDIM + h * HDIM + sub * 8);
    uint4 ka = *(const uint4*)(k + (size_t)s * QKDIM + h * HDIM + sub * 8);
    float dot = dot8h(qa, ka);
    dot += __shfl_down_sync(0xffffffffu, dot, 4, 8);
    dot += __shfl_down_sync(0xffffffffu, dot, 2, 8);
    dot += __shfl_down_sync(0xffffffffu, dot, 1, 8);
    // head sums live in lanes 0,8,16,24 -> broadcast to lane 0
    float d0 = __shfl_sync(0xffffffffu, dot, 0);
    float d1 = __shfl_sync(0xffffffffu, dot, 8);
    float d2 = __shfl_sync(0xffffffffu, dot, 16);
    float d3 = __shfl_sync(0xffffffffu, dot, 24);
    if (lane == 0) {
        float e0 = __expf(d0 * 0.125f);
        float e1 = __expf(d1 * 0.125f);
        float e2 = __expf(d2 * 0.125f);
        float e3 = __expf(d3 * 0.125f);
        *(float4*)(score + (size_t)warp * NHEADS) = make_float4(e0, e1, e2, e3);
        red_add_v4(denom + (size_t)d * NHEADS, e0, e1, e2, e3);
    }
}

// ---------------- aggregation: 2 edges per warp, v4 vector atomics (R14) ----------
__global__ void agg_kernel(const int* __restrict__ esrc, const int* __restrict__ edst,
                           const float* __restrict__ sc, const float* __restrict__ den,
                           const __half* __restrict__ v, float* __restrict__ out, int nedge) {
    int gw = (blockIdx.x * blockDim.x + threadIdx.x) >> 5;
    int lane = threadIdx.x & 31;
    int e = gw * 2 + (lane >> 4);
    if (e >= nedge) return;
    int li = lane & 15;                        // output floats [li*4, li*4+4)

    int s = esrc[e], d = edst[e];
    float4 scv = *(const float4*)(sc + (size_t)e * NHEADS);
    float4 dnv = *(const float4*)(den + (size_t)d * NHEADS);
    float a0 = 0.25f * scv.x / dnv.x;
    float a1 = 0.25f * scv.y / dnv.y;
    float a2 = 0.25f * scv.z / dnv.z;
    float a3 = 0.25f * scv.w / dnv.w;

    const __half* vb = v + (size_t)s * QKDIM + li * 4;
    uint2 r0 = *(const uint2*)(vb);
    uint2 r1 = *(const uint2*)(vb + 64);
    uint2 r2 = *(const uint2*)(vb + 128);
    uint2 r3 = *(const uint2*)(vb + 192);
    const __half2* h0 = (const __half2*)&r0;
    const __half2* h1 = (const __half2*)&r1;
    const __half2* h2 = (const __half2*)&r2;
    const __half2* h3 = (const __half2*)&r3;
    float2 v0a = __half22float2(h0[0]), v0b = __half22float2(h0[1]);
    float2 v1a = __half22float2(h1[0]), v1b = __half22float2(h1[1]);
    float2 v2a = __half22float2(h2[0]), v2b = __half22float2(h2[1]);
    float2 v3a = __half22float2(h3[0]), v3b = __half22float2(h3[1]);

    float o0 = a0 * v0a.x + a1 * v1a.x + a2 * v2a.x + a3 * v3a.x;
    float o1 = a0 * v0a.y + a1 * v1a.y + a2 * v2a.y + a3 * v3a.y;
    float o2 = a0 * v0b.x + a1 * v1b.x + a2 * v2b.x + a3 * v3b.x;
    float o3 = a0 * v0b.y + a1 * v1b.y + a2 * v2b.y + a3 * v3b.y;

    red_add_v4(out + (size_t)d * HDIM + li * 4, o0, o1, o2, o3);
}

// ---------------- classifier ----------------
__global__ void pred_kernel(const int* __restrict__ l0, const int* __restrict__ l1,
                            const float* __restrict__ xs, const float* __restrict__ xt,
                            float* __restrict__ out, int n) {
    int gid = blockIdx.x * blockDim.x + threadIdx.x;
    int pair = gid >> 3, sub = gid & 7;
    if (pair >= n) return;
    int a = l0[pair], b = l1[pair];
    const float4* xa = (const float4*)(xs + (size_t)a * HDIM);
    const float4* xb = (const float4*)(xt + (size_t)b * HDIM);
    float4 p0 = xa[sub * 2], p1 = xa[sub * 2 + 1];
    float4 q0 = xb[sub * 2], q1 = xb[sub * 2 + 1];
    float dot = p0.x * q0.x + p0.y * q0.y + p0.z * q0.z + p0.w * q0.w
              + p1.x * q1.x + p1.y * q1.y + p1.z * q1.z + p1.w * q1.w;
    dot += __shfl_down_sync(0xffffffffu, dot, 4, 8);
    dot += __shfl_down_sync(0xffffffffu, dot, 2, 8);
    dot += __shfl_down_sync(0xffffffffu, dot, 1, 8);
    if (sub == 0) out[pair] = dot;
}

// ---------------- launch ----------------
extern "C" void kernel_launch(void* const* d_in, const int* in_sizes, int n_in,
                              void* d_out, int out_size) {
    const float* src_emb = (const float*)d_in[0];
    const float* tgt_emb = (const float*)d_in[1];
    const float* Wq = (const float*)d_in[2];
    const float* bq = (const float*)d_in[3];
    const float* Wk = (const float*)d_in[4];
    const float* bk = (const float*)d_in[5];
    const float* Wv = (const float*)d_in[6];
    const float* bv = (const float*)d_in[7];
    const float* Ws = (const float*)d_in[8];
    const float* bs = (const float*)d_in[9];
    const int* nid_s = (const int*)d_in[10];
    const int* nid_t = (const int*)d_in[11];
    const int* e_st  = (const int*)d_in[12];
    const int* e_ts  = (const int*)d_in[13];
    const int* lbl   = (const int*)d_in[14];
    float* out = (float*)d_out;

    float *xs_a, *xs_b, *xt_a, *xt_b, *sc_st, *sc_ts, *d_st, *d_ts;
    __half *q_st, *k_ts, *v_ts, *q_ts, *k_st, *v_st, *xsh, *xth;
    cudaGetSymbolAddress((void**)&xs_a, g_xs_a);
    cudaGetSymbolAddress((void**)&xs_b, g_xs_b);
    cudaGetSymbolAddress((void**)&xt_a, g_xt_a);
    cudaGetSymbolAddress((void**)&xt_b, g_xt_b);
    cudaGetSymbolAddress((void**)&q_st, g_q_st);
    cudaGetSymbolAddress((void**)&k_ts, g_k_ts);
    cudaGetSymbolAddress((void**)&v_ts, g_v_ts);
    cudaGetSymbolAddress((void**)&q_ts, g_q_ts);
    cudaGetSymbolAddress((void**)&k_st, g_k_st);
    cudaGetSymbolAddress((void**)&v_st, g_v_st);
    cudaGetSymbolAddress((void**)&sc_st, g_sc_st);
    cudaGetSymbolAddress((void**)&sc_ts, g_sc_ts);
    cudaGetSymbolAddress((void**)&d_st, g_d_st);
    cudaGetSymbolAddress((void**)&d_ts, g_d_ts);
    cudaGetSymbolAddress((void**)&xsh, g_xsh);
    cudaGetSymbolAddress((void**)&xth, g_xth);

    const int SMEM = (128 * PADK + 64 * PADK * 2) * 2;  // 36864 B
    cudaFuncSetAttribute(proj_mma, cudaFuncAttributeMaxDynamicSharedMemorySize, SMEM);

    int nz0 = (N_TGT + N_SRC) * NHEADS;
    int nx = (N_SRC + N_TGT) * HDIM;
    zero2_kernel<<<(nz0 + 255) / 256, 256>>>(d_st, N_TGT * NHEADS, d_ts, N_SRC * NHEADS);
    gather_h2<<<(nx + 255) / 256, 256>>>(src_emb, tgt_emb, nid_s, nid_t);
    split_w<<<(4 * WSECT + 255) / 256, 256>>>(Wq, Wk, Wv, Ws);

    int sb = (N_E * 32 + 255) / 256;              // one warp per edge (scoreexp)
    int ab = (((N_E + 1) / 2) * 32 + 255) / 256;  // two edges per warp (agg)

    for (int l = 0; l < 2; l++) {
        float* out_s = l ? xs_a : xs_b;
        float* out_t = l ? xt_a : xt_b;
        if (l) {
            relu_h2<<<(nx + 255) / 256, 256>>>();
            zero2_kernel<<<(nz0 + 255) / 256, 256>>>(d_st, N_TGT * NHEADS, d_ts, N_SRC * NHEADS);
        }

        int le0 = l * 2 + 0, le1 = l * 2 + 1;
        dim3 gs((N_SRC + 127) / 128, 4), gt((N_TGT + 127) / 128, 4);
        // src-side: k_st(Wk l,0), v_st(Wv l,0), q_ts(Wq l,1), skip(Ws l,1)
        proj_mma<<<gs, 256, SMEM>>>(xsh, N_SRC,
            le0 * WSECT + 256 * 64, le0 * WSECT + 512 * 64,
            le1 * WSECT + 0,        le1 * WSECT + 768 * 64,
            bk + le0 * 256, bv + le0 * 256, bq + le1 * 256, bs + le1 * 64,
            k_st, v_st, q_ts, out_s);
        // tgt-side: q_st(Wq l,0), k_ts(Wk l,1), v_ts(Wv l,1), skip(Ws l,0)
        proj_mma<<<gt, 256, SMEM>>>(xth, N_TGT,
            le0 * WSECT + 0,        le1 * WSECT + 256 * 64,
            le1 * WSECT + 512 * 64, le0 * WSECT + 768 * 64,
            bq + le0 * 256, bk + le1 * 256, bv + le1 * 256, bs + le0 * 64,
            q_st, k_ts, v_ts, out_t);

        scoreexp_kernel<<<sb, 256>>>(e_st, e_st + N_E, q_st, k_st, sc_st, d_st, N_E);
        scoreexp_kernel<<<sb, 256>>>(e_ts, e_ts + N_E, q_ts, k_ts, sc_ts, d_ts, N_E);

        agg_kernel<<<ab, 256>>>(e_st, e_st + N_E, sc_st, d_st, v_st, out_t, N_E);
        agg_kernel<<<ab, 256>>>(e_ts, e_ts + N_E, sc_ts, d_ts, v_ts, out_s, N_E);
    }

    pred_kernel<<<(N_LBL * 8 + 255) / 256, 256>>>(lbl, lbl + N_LBL, xs_a, xt_a, out, N_LBL);
}

// round 16
// speedup vs baseline: 1.1125x; 1.1125x over previous
#include <cuda_runtime.h>
#include <cuda_fp16.h>

#define HDIM   64
#define NHEADS 4
#define QKDIM  256           // NHEADS * HDIM
#define N_SRC  50000
#define N_TGT  10000
#define N_E    250000
#define N_LBL  200000

#define PADK   72            // smem row stride in fp16 (144B): ldmatrix conflict-free
#define WSECT  (832 * 64)    // per (layer,edge_type) transposed weight block (elements)

// ---------------- scratch (static device memory; no allocations) ----------------
__device__ float g_xs_a[N_SRC * HDIM];
__device__ float g_xs_b[N_SRC * HDIM];
__device__ float g_xt_a[N_TGT * HDIM];
__device__ float g_xt_b[N_TGT * HDIM];

// fp16 edge operands
__device__ __align__(16) __half g_q_st[N_TGT * QKDIM];
__device__ __align__(16) __half g_k_ts[N_TGT * QKDIM];
__device__ __align__(16) __half g_v_ts[N_TGT * QKDIM];
__device__ __align__(16) __half g_q_ts[N_SRC * QKDIM];
__device__ __align__(16) __half g_k_st[N_SRC * QKDIM];
__device__ __align__(16) __half g_v_st[N_SRC * QKDIM];

__device__ __align__(16) float g_sc_st[N_E * NHEADS];
__device__ __align__(16) float g_sc_ts[N_E * NHEADS];
__device__ __align__(16) float g_d_st[N_TGT * NHEADS];
__device__ __align__(16) float g_d_ts[N_SRC * NHEADS];

// A operand: fp16. B: split-fp16 (hi + residual).
__device__ __align__(16) __half g_xsh[N_SRC * HDIM];
__device__ __align__(16) __half g_xth[N_TGT * HDIM];
__device__ __align__(16) __half g_wth[4 * WSECT];
__device__ __align__(16) __half g_wtl[4 * WSECT];

// ---------------- helpers ----------------
__device__ __forceinline__ void split2h(float v, __half& h, __half& l) {
    h = __float2half_rn(v);
    l = __float2half_rn(v - __half2float(h));
}
__device__ __forceinline__ unsigned su32(const void* p) {
    unsigned a;
    asm("{ .reg .u64 t; cvta.to.shared.u64 t, %1; cvt.u32.u64 %0, t; }" : "=r"(a) : "l"(p));
    return a;
}
__device__ __forceinline__ void ldsm4(unsigned& r0, unsigned& r1, unsigned& r2, unsigned& r3,
                                      unsigned addr) {
    asm volatile("ldmatrix.sync.aligned.m8n8.x4.shared.b16 {%0,%1,%2,%3}, [%4];"
                 : "=r"(r0), "=r"(r1), "=r"(r2), "=r"(r3) : "r"(addr));
}
__device__ __forceinline__ void mma16816h(float* d, const unsigned* a, unsigned b0, unsigned b1) {
    asm volatile("mma.sync.aligned.m16n8k16.row.col.f32.f16.f16.f32 "
                 "{%0,%1,%2,%3}, {%4,%5,%6,%7}, {%8,%9}, {%0,%1,%2,%3};"
                 : "+f"(d[0]), "+f"(d[1]), "+f"(d[2]), "+f"(d[3])
                 : "r"(a[0]), "r"(a[1]), "r"(a[2]), "r"(a[3]), "r"(b0), "r"(b1));
}
__device__ __forceinline__ float dot8h(uint4 qa, uint4 ka) {
    const __half2* qh = (const __half2*)&qa;
    const __half2* kh = (const __half2*)&ka;
    float dot = 0.0f;
    #pragma unroll
    for (int i = 0; i < 4; i++) {
        float2 a = __half22float2(qh[i]);
        float2 b = __half22float2(kh[i]);
        dot += a.x * b.x + a.y * b.y;
    }
    return dot;
}
// vector reduction add (sm_90+): one 16B atomic instead of 4 scalar ones
__device__ __forceinline__ void red_add_v4(float* p, float a, float b, float c, float d) {
    asm volatile("red.global.add.v4.f32 [%0], {%1, %2, %3, %4};"
                 :: "l"(p), "f"(a), "f"(b), "f"(c), "f"(d) : "memory");
}

// ---------------- small kernels ----------------
__global__ void zero2_kernel(float* __restrict__ a, int na, float* __restrict__ b, int nb) {
    int i = blockIdx.x * blockDim.x + threadIdx.x;
    if (i < na) { a[i] = 0.0f; return; }
    i -= na;
    if (i < nb) b[i] = 0.0f;
}

__global__ void gather_h2(const float* __restrict__ semb, const float* __restrict__ temb,
                          const int* __restrict__ sid, const int* __restrict__ tid) {
    int i = blockIdx.x * blockDim.x + threadIdx.x;
    if (i < N_SRC * HDIM) {
        int row = i >> 6, d = i & 63;
        g_xsh[i] = __float2half_rn(semb[(size_t)sid[row] * HDIM + d]);
    } else if (i < (N_SRC + N_TGT) * HDIM) {
        int j = i - N_SRC * HDIM;
        int row = j >> 6, d = j & 63;
        g_xth[j] = __float2half_rn(temb[(size_t)tid[row] * HDIM + d]);
    }
}

__global__ void relu_h2() {
    int i = blockIdx.x * blockDim.x + threadIdx.x;
    if (i < N_SRC * HDIM) {
        g_xsh[i] = __float2half_rn(fmaxf(g_xs_b[i], 0.0f));
    } else if (i < (N_SRC + N_TGT) * HDIM) {
        int j = i - N_SRC * HDIM;
        g_xth[j] = __float2half_rn(fmaxf(g_xt_b[j], 0.0f));
    }
}

__global__ void split_w(const float* __restrict__ Wq, const float* __restrict__ Wk,
                        const float* __restrict__ Wv, const float* __restrict__ Ws) {
    int i = blockIdx.x * blockDim.x + threadIdx.x;
    if (i >= 4 * WSECT) return;
    int le = i / WSECT, rem = i % WSECT;
    int n = rem >> 6, k = rem & 63;
    float v;
    if (n < 256)      v = Wq[(size_t)le * 64 * 256 + k * 256 + n];
    else if (n < 512) v = Wk[(size_t)le * 64 * 256 + k * 256 + (n - 256)];
    else if (n < 768) v = Wv[(size_t)le * 64 * 256 + k * 256 + (n - 512)];
    else              v = Ws[(size_t)le * 64 * 64 + k * 64 + (n - 768)];
    split2h(v, g_wth[i], g_wtl[i]);
}

// ---------------- tensor-core projection GEMM, permuted-B vector epilogue ------
// B staged with column field-swap (phys nt*8+q*2+b holds logical q*8+nt*2+b) so
// each thread's 8 accumulators cover 8 consecutive logical output columns.
__global__ void __launch_bounds__(256) proj_mma(
    const __half* __restrict__ Xh, int N,
    int off0, int off1, int off2, int off3,
    const float* __restrict__ b0, const float* __restrict__ b1,
    const float* __restrict__ b2, const float* __restrict__ b3,
    __half* __restrict__ o0, __half* __restrict__ o1,
    __half* __restrict__ o2, float* __restrict__ o3) {
    extern __shared__ __half sm[];
    __half* Ah = sm;                           // [128][PADK]
    __half* Bh = Ah + 128 * PADK;              // [64][PADK]
    __half* Bl = Bh + 64 * PADK;

    int sec = blockIdx.y;                      // 0..3
    int woff_base, ncb; const float* bias; __half* outh = 0; float* outf = 0;
    if (sec == 0)      { woff_base = off0; bias = b0; outh = o0; ncb = 4; }
    else if (sec == 1) { woff_base = off1; bias = b1; outh = o1; ncb = 4; }
    else if (sec == 2) { woff_base = off2; bias = b2; outh = o2; ncb = 4; }
    else               { woff_base = off3; bias = b3; outf = o3; ncb = 1; }

    int t = threadIdx.x;
    int rowbase = blockIdx.x * 128;

    const uint4* xh4 = (const uint4*)Xh;
    uint4 z4 = make_uint4(0u, 0u, 0u, 0u);
    #pragma unroll
    for (int i = 0; i < 4; i++) {
        int idx = t + i * 256;
        int r = idx >> 3, c = idx & 7;
        int gr = rowbase + r;
        uint4 vh = z4;
        if (gr < N) vh = xh4[(size_t)gr * 8 + c];
        *(uint4*)(Ah + r * PADK + c * 8) = vh;
    }

    int lane = t & 31, warp = t >> 5;
    int wr = warp >> 1, wc = warp & 1;
    int lrow = lane & 7, lsel = lane >> 3;
    int q4 = lane & 3;
    unsigned ah_u = su32(Ah), bh_u = su32(Bh), bl_u = su32(Bl);

    for (int lcb = 0; lcb < ncb; lcb++) {
        if (lcb) __syncthreads();
        int woff = woff_base + lcb * 64 * 64;
        const uint4* wh4 = (const uint4*)(g_wth + woff);
        const uint4* wl4 = (const uint4*)(g_wtl + woff);
        #pragma unroll
        for (int i = 0; i < 2; i++) {
            int idx = t + i * 256;
            int p = idx >> 3, c = idx & 7;
            // field-swap permutation within each 32-col warp tile
            int wcp = p >> 5, inner = p & 31;
            int nlog = wcp * 32 + ((inner >> 1) & 3) * 8 + (inner >> 3) * 2 + (inner & 1);
            *(uint4*)(Bh + p * PADK + c * 8) = wh4[nlog * 8 + c];
            *(uint4*)(Bl + p * PADK + c * 8) = wl4[nlog * 8 + c];
        }
        __syncthreads();

        float acc[2][4][4];
        #pragma unroll
        for (int mt = 0; mt < 2; mt++)
            #pragma unroll
            for (int nt = 0; nt < 4; nt++)
                #pragma unroll
                for (int r = 0; r < 4; r++) acc[mt][nt][r] = 0.0f;

        #pragma unroll
        for (int kc = 0; kc < 4; kc++) {
            int k0 = kc * 16;
            unsigned ah[2][4], bh[2][4], bl[2][4];
            #pragma unroll
            for (int mt = 0; mt < 2; mt++) {
                int row = wr * 32 + mt * 16 + (lsel & 1) * 8 + lrow;
                int koff = k0 + (lsel >> 1) * 8;
                unsigned boff = (unsigned)(row * PADK + koff) * 2u;
                ldsm4(ah[mt][0], ah[mt][1], ah[mt][2], ah[mt][3], ah_u + boff);
            }
            #pragma unroll
            for (int nt2 = 0; nt2 < 2; nt2++) {
                int n = wc * 32 + nt2 * 16 + (lsel >> 1) * 8 + lrow;
                int koff = k0 + (lsel & 1) * 8;
                unsigned boff = (unsigned)(n * PADK + koff) * 2u;
                ldsm4(bh[nt2][0], bh[nt2][1], bh[nt2][2], bh[nt2][3], bh_u + boff);
                ldsm4(bl[nt2][0], bl[nt2][1], bl[nt2][2], bl[nt2][3], bl_u + boff);
            }
            #pragma unroll
            for (int mt = 0; mt < 2; mt++)
                #pragma unroll
                for (int nt = 0; nt < 4; nt++) {
                    int g = nt >> 1, hf = (nt & 1) * 2;
                    mma16816h(acc[mt][nt], ah[mt], bh[g][hf], bh[g][hf + 1]);
                    mma16816h(acc[mt][nt], ah[mt], bl[g][hf], bl[g][hf + 1]);
                }
        }

        // epilogue: thread owns 8 consecutive logical cols [colb, colb+8)
        int colb = lcb * 64 + wc * 32 + q4 * 8;
        float4 bv0 = *(const float4*)(bias + colb);
        float4 bv1 = *(const float4*)(bias + colb + 4);
        #pragma unroll
        for (int mt = 0; mt < 2; mt++) {
            int ra = rowbase + wr * 32 + mt * 16 + (lane >> 2);
            int rb = ra + 8;
            if (sec < 3) {
                uint4 sa, sb;
                __half2* pa = (__half2*)&sa;
                __half2* pb = (__half2*)&sb;
                pa[0] = __floats2half2_rn(acc[mt][0][0] + bv0.x, acc[mt][0][1] + bv0.y);
                pa[1] = __floats2half2_rn(acc[mt][1][0] + bv0.z, acc[mt][1][1] + bv0.w);
                pa[2] = __floats2half2_rn(acc[mt][2][0] + bv1.x, acc[mt][2][1] + bv1.y);
                pa[3] = __floats2half2_rn(acc[mt][3][0] + bv1.z, acc[mt][3][1] + bv1.w);
                pb[0] = __floats2half2_rn(acc[mt][0][2] + bv0.x, acc[mt][0][3] + bv0.y);
                pb[1] = __floats2half2_rn(acc[mt][1][2] + bv0.z, acc[mt][1][3] + bv0.w);
                pb[2] = __floats2half2_rn(acc[mt][2][2] + bv1.x, acc[mt][2][3] + bv1.y);
                pb[3] = __floats2half2_rn(acc[mt][3][2] + bv1.z, acc[mt][3][3] + bv1.w);
                if (ra < N) *(uint4*)(outh + (size_t)ra * 256 + colb) = sa;
                if (rb < N) *(uint4*)(outh + (size_t)rb * 256 + colb) = sb;
            } else {
                float4 fa0 = make_float4(acc[mt][0][0] + bv0.x, acc[mt][0][1] + bv0.y,
                                         acc[mt][1][0] + bv0.z, acc[mt][1][1] + bv0.w);
                float4 fa1 = make_float4(acc[mt][2][0] + bv1.x, acc[mt][2][1] + bv1.y,
                                         acc[mt][3][0] + bv1.z, acc[mt][3][1] + bv1.w);
                float4 fb0 = make_float4(acc[mt][0][2] + bv0.x, acc[mt][0][3] + bv0.y,
                                         acc[mt][1][2] + bv0.z, acc[mt][1][3] + bv0.w);
                float4 fb1 = make_float4(acc[mt][2][2] + bv1.x, acc[mt][2][3] + bv1.y,
                                         acc[mt][3][2] + bv1.z, acc[mt][3][3] + bv1.w);
                if (ra < N) {
                    *(float4*)(outf + (size_t)ra * 64 + colb) = fa0;
                    *(float4*)(outf + (size_t)ra * 64 + colb + 4) = fa1;
                }
                if (rb < N) {
                    *(float4*)(outf + (size_t)rb * 64 + colb) = fb0;
                    *(float4*)(outf + (size_t)rb * 64 + colb + 4) = fb1;
                }
            }
        }
    }
}

// ---------------- fused score+exp+denom pass (exact R14 champion) ----------------
__global__ void scoreexp_kernel(const int* __restrict__ esrc, const int* __restrict__ edst,
                                const __half* __restrict__ q, const __half* __restrict__ k,
                                float* __restrict__ score, float* __restrict__ denom,
                                int nedge) {
    int warp = (blockIdx.x * blockDim.x + threadIdx.x) >> 5;
    if (warp >= nedge) return;
    int lane = threadIdx.x & 31;
    int s = esrc[warp], d = edst[warp];
    int h = lane >> 3, sub = lane & 7;
    uint4 qa = *(const uint4*)(q + (size_t)d * QKDIM + h * HDIM + sub * 8);
    uint4 ka = *(const uint4*)(k + (size_t)s * QKDIM + h * HDIM + sub * 8);
    float dot = dot8h(qa, ka);
    dot += __shfl_down_sync(0xffffffffu, dot, 4, 8);
    dot += __shfl_down_sync(0xffffffffu, dot, 2, 8);
    dot += __shfl_down_sync(0xffffffffu, dot, 1, 8);
    if (sub == 0) {
        float ex = __expf(dot * 0.125f);
        score[(size_t)warp * NHEADS + h] = ex;
        atomicAdd(&denom[(size_t)d * NHEADS + h], ex);
    }
}

// ---------------- aggregation: 2 edges per warp, v4 vector atomics (R14) ----------
__global__ void agg_kernel(const int* __restrict__ esrc, const int* __restrict__ edst,
                           const float* __restrict__ sc, const float* __restrict__ den,
                           const __half* __restrict__ v, float* __restrict__ out, int nedge) {
    int gw = (blockIdx.x * blockDim.x + threadIdx.x) >> 5;
    int lane = threadIdx.x & 31;
    int e = gw * 2 + (lane >> 4);
    if (e >= nedge) return;
    int li = lane & 15;                        // output floats [li*4, li*4+4)

    int s = esrc[e], d = edst[e];
    float4 scv = *(const float4*)(sc + (size_t)e * NHEADS);
    float4 dnv = *(const float4*)(den + (size_t)d * NHEADS);
    float a0 = 0.25f * scv.x / dnv.x;
    float a1 = 0.25f * scv.y / dnv.y;
    float a2 = 0.25f * scv.z / dnv.z;
    float a3 = 0.25f * scv.w / dnv.w;

    const __half* vb = v + (size_t)s * QKDIM + li * 4;
    uint2 r0 = *(const uint2*)(vb);
    uint2 r1 = *(const uint2*)(vb + 64);
    uint2 r2 = *(const uint2*)(vb + 128);
    uint2 r3 = *(const uint2*)(vb + 192);
    const __half2* h0 = (const __half2*)&r0;
    const __half2* h1 = (const __half2*)&r1;
    const __half2* h2 = (const __half2*)&r2;
    const __half2* h3 = (const __half2*)&r3;
    float2 v0a = __half22float2(h0[0]), v0b = __half22float2(h0[1]);
    float2 v1a = __half22float2(h1[0]), v1b = __half22float2(h1[1]);
    float2 v2a = __half22float2(h2[0]), v2b = __half22float2(h2[1]);
    float2 v3a = __half22float2(h3[0]), v3b = __half22float2(h3[1]);

    float o0 = a0 * v0a.x + a1 * v1a.x + a2 * v2a.x + a3 * v3a.x;
    float o1 = a0 * v0a.y + a1 * v1a.y + a2 * v2a.y + a3 * v3a.y;
    float o2 = a0 * v0b.x + a1 * v1b.x + a2 * v2b.x + a3 * v3b.x;
    float o3 = a0 * v0b.y + a1 * v1b.y + a2 * v2b.y + a3 * v3b.y;

    red_add_v4(out + (size_t)d * HDIM + li * 4, o0, o1, o2, o3);
}

// ---------------- classifier ----------------
__global__ void pred_kernel(const int* __restrict__ l0, const int* __restrict__ l1,
                            const float* __restrict__ xs, const float* __restrict__ xt,
                            float* __restrict__ out, int n) {
    int gid = blockIdx.x * blockDim.x + threadIdx.x;
    int pair = gid >> 3, sub = gid & 7;
    if (pair >= n) return;
    int a = l0[pair], b = l1[pair];
    const float4* xa = (const float4*)(xs + (size_t)a * HDIM);
    const float4* xb = (const float4*)(xt + (size_t)b * HDIM);
    float4 p0 = xa[sub * 2], p1 = xa[sub * 2 + 1];
    float4 q0 = xb[sub * 2], q1 = xb[sub * 2 + 1];
    float dot = p0.x * q0.x + p0.y * q0.y + p0.z * q0.z + p0.w * q0.w
              + p1.x * q1.x + p1.y * q1.y + p1.z * q1.z + p1.w * q1.w;
    dot += __shfl_down_sync(0xffffffffu, dot, 4, 8);
    dot += __shfl_down_sync(0xffffffffu, dot, 2, 8);
    dot += __shfl_down_sync(0xffffffffu, dot, 1, 8);
    if (sub == 0) out[pair] = dot;
}

// ---------------- launch ----------------
extern "C" void kernel_launch(void* const* d_in, const int* in_sizes, int n_in,
                              void* d_out, int out_size) {
    const float* src_emb = (const float*)d_in[0];
    const float* tgt_emb = (const float*)d_in[1];
    const float* Wq = (const float*)d_in[2];
    const float* bq = (const float*)d_in[3];
    const float* Wk = (const float*)d_in[4];
    const float* bk = (const float*)d_in[5];
    const float* Wv = (const float*)d_in[6];
    const float* bv = (const float*)d_in[7];
    const float* Ws = (const float*)d_in[8];
    const float* bs = (const float*)d_in[9];
    const int* nid_s = (const int*)d_in[10];
    const int* nid_t = (const int*)d_in[11];
    const int* e_st  = (const int*)d_in[12];
    const int* e_ts  = (const int*)d_in[13];
    const int* lbl   = (const int*)d_in[14];
    float* out = (float*)d_out;

    float *xs_a, *xs_b, *xt_a, *xt_b, *sc_st, *sc_ts, *d_st, *d_ts;
    __half *q_st, *k_ts, *v_ts, *q_ts, *k_st, *v_st, *xsh, *xth;
    cudaGetSymbolAddress((void**)&xs_a, g_xs_a);
    cudaGetSymbolAddress((void**)&xs_b, g_xs_b);
    cudaGetSymbolAddress((void**)&xt_a, g_xt_a);
    cudaGetSymbolAddress((void**)&xt_b, g_xt_b);
    cudaGetSymbolAddress((void**)&q_st, g_q_st);
    cudaGetSymbolAddress((void**)&k_ts, g_k_ts);
    cudaGetSymbolAddress((void**)&v_ts, g_v_ts);
    cudaGetSymbolAddress((void**)&q_ts, g_q_ts);
    cudaGetSymbolAddress((void**)&k_st, g_k_st);
    cudaGetSymbolAddress((void**)&v_st, g_v_st);
    cudaGetSymbolAddress((void**)&sc_st, g_sc_st);
    cudaGetSymbolAddress((void**)&sc_ts, g_sc_ts);
    cudaGetSymbolAddress((void**)&d_st, g_d_st);
    cudaGetSymbolAddress((void**)&d_ts, g_d_ts);
    cudaGetSymbolAddress((void**)&xsh, g_xsh);
    cudaGetSymbolAddress((void**)&xth, g_xth);

    const int SMEM = (128 * PADK + 64 * PADK * 2) * 2;  // 36864 B
    cudaFuncSetAttribute(proj_mma, cudaFuncAttributeMaxDynamicSharedMemorySize, SMEM);

    int nz0 = (N_TGT + N_SRC) * NHEADS;
    int nx = (N_SRC + N_TGT) * HDIM;
    zero2_kernel<<<(nz0 + 255) / 256, 256>>>(d_st, N_TGT * NHEADS, d_ts, N_SRC * NHEADS);
    gather_h2<<<(nx + 255) / 256, 256>>>(src_emb, tgt_emb, nid_s, nid_t);
    split_w<<<(4 * WSECT + 255) / 256, 256>>>(Wq, Wk, Wv, Ws);

    int sb = (N_E * 32 + 255) / 256;              // one warp per edge (scoreexp)
    int ab = (((N_E + 1) / 2) * 32 + 255) / 256;  // two edges per warp (agg)

    for (int l = 0; l < 2; l++) {
        float* out_s = l ? xs_a : xs_b;
        float* out_t = l ? xt_a : xt_b;
        if (l) {
            relu_h2<<<(nx + 255) / 256, 256>>>();
            zero2_kernel<<<(nz0 + 255) / 256, 256>>>(d_st, N_TGT * NHEADS, d_ts, N_SRC * NHEADS);
        }

        int le0 = l * 2 + 0, le1 = l * 2 + 1;
        dim3 gs((N_SRC + 127) / 128, 4), gt((N_TGT + 127) / 128, 4);
        // src-side: k_st(Wk l,0), v_st(Wv l,0), q_ts(Wq l,1), skip(Ws l,1)
        proj_mma<<<gs, 256, SMEM>>>(xsh, N_SRC,
            le0 * WSECT + 256 * 64, le0 * WSECT + 512 * 64,
            le1 * WSECT + 0,        le1 * WSECT + 768 * 64,
            bk + le0 * 256, bv + le0 * 256, bq + le1 * 256, bs + le1 * 64,
            k_st, v_st, q_ts, out_s);
        // tgt-side: q_st(Wq l,0), k_ts(Wk l,1), v_ts(Wv l,1), skip(Ws l,0)
        proj_mma<<<gt, 256, SMEM>>>(xth, N_TGT,
            le0 * WSECT + 0,        le1 * WSECT + 256 * 64,
            le1 * WSECT + 512 * 64, le0 * WSECT + 768 * 64,
            bq + le0 * 256, bk + le1 * 256, bv + le1 * 256, bs + le0 * 64,
            q_st, k_ts, v_ts, out_t);

        scoreexp_kernel<<<sb, 256>>>(e_st, e_st + N_E, q_st, k_st, sc_st, d_st, N_E);
        scoreexp_kernel<<<sb, 256>>>(e_ts, e_ts + N_E, q_ts, k_ts, sc_ts, d_ts, N_E);

        agg_kernel<<<ab, 256>>>(e_st, e_st + N_E, sc_st, d_st, v_st, out_t, N_E);
        agg_kernel<<<ab, 256>>>(e_ts, e_ts + N_E, sc_ts, d_ts, v_ts, out_s, N_E);
    }

    pred_kernel<<<(N_LBL * 8 + 255) / 256, 256>>>(lbl, lbl + N_LBL, xs_a, xt_a, out, N_LBL);
}

// round 17
// speedup vs baseline: 1.2801x; 1.1507x over previous
#include <cuda_runtime.h>
#include <cuda_fp16.h>

#define HDIM   64
#define NHEADS 4
#define QKDIM  256           // NHEADS * HDIM
#define N_SRC  50000
#define N_TGT  10000
#define N_E    250000
#define N_LBL  200000

#define PADK   72            // smem row stride in fp16 (144B): ldmatrix conflict-free
#define WSECT  (832 * 64)    // per (layer,edge_type) transposed weight block (elements)

// ---------------- scratch (static device memory; no allocations) ----------------
__device__ float g_xs_a[N_SRC * HDIM];
__device__ float g_xs_b[N_SRC * HDIM];
__device__ float g_xt_a[N_TGT * HDIM];
__device__ float g_xt_b[N_TGT * HDIM];

// fp16 edge operands
__device__ __align__(16) __half g_q_st[N_TGT * QKDIM];
__device__ __align__(16) __half g_k_ts[N_TGT * QKDIM];
__device__ __align__(16) __half g_v_ts[N_TGT * QKDIM];
__device__ __align__(16) __half g_q_ts[N_SRC * QKDIM];
__device__ __align__(16) __half g_k_st[N_SRC * QKDIM];
__device__ __align__(16) __half g_v_st[N_SRC * QKDIM];

__device__ __align__(16) float g_sc_st[N_E * NHEADS];
__device__ __align__(16) float g_sc_ts[N_E * NHEADS];
__device__ __align__(16) float g_d_st[N_TGT * NHEADS];
__device__ __align__(16) float g_d_ts[N_SRC * NHEADS];

// A operand: fp16. B: split-fp16 (hi + residual).
__device__ __align__(16) __half g_xsh[N_SRC * HDIM];
__device__ __align__(16) __half g_xth[N_TGT * HDIM];
__device__ __align__(16) __half g_wth[4 * WSECT];
__device__ __align__(16) __half g_wtl[4 * WSECT];

// ---------------- helpers ----------------
__device__ __forceinline__ void split2h(float v, __half& h, __half& l) {
    h = __float2half_rn(v);
    l = __float2half_rn(v - __half2float(h));
}
__device__ __forceinline__ unsigned su32(const void* p) {
    unsigned a;
    asm("{ .reg .u64 t; cvta.to.shared.u64 t, %1; cvt.u32.u64 %0, t; }" : "=r"(a) : "l"(p));
    return a;
}
__device__ __forceinline__ void ldsm4(unsigned& r0, unsigned& r1, unsigned& r2, unsigned& r3,
                                      unsigned addr) {
    asm volatile("ldmatrix.sync.aligned.m8n8.x4.shared.b16 {%0,%1,%2,%3}, [%4];"
                 : "=r"(r0), "=r"(r1), "=r"(r2), "=r"(r3) : "r"(addr));
}
__device__ __forceinline__ void mma16816h(float* d, const unsigned* a, unsigned b0, unsigned b1) {
    asm volatile("mma.sync.aligned.m16n8k16.row.col.f32.f16.f16.f32 "
                 "{%0,%1,%2,%3}, {%4,%5,%6,%7}, {%8,%9}, {%0,%1,%2,%3};"
                 : "+f"(d[0]), "+f"(d[1]), "+f"(d[2]), "+f"(d[3])
                 : "r"(a[0]), "r"(a[1]), "r"(a[2]), "r"(a[3]), "r"(b0), "r"(b1));
}
__device__ __forceinline__ float dot8h(uint4 qa, uint4 ka) {
    const __half2* qh = (const __half2*)&qa;
    const __half2* kh = (const __half2*)&ka;
    float dot = 0.0f;
    #pragma unroll
    for (int i = 0; i < 4; i++) {
        float2 a = __half22float2(qh[i]);
        float2 b = __half22float2(kh[i]);
        dot += a.x * b.x + a.y * b.y;
    }
    return dot;
}
// vector reduction add (sm_90+): one 16B atomic instead of 4 scalar ones
__device__ __forceinline__ void red_add_v4(float* p, float a, float b, float c, float d) {
    asm volatile("red.global.add.v4.f32 [%0], {%1, %2, %3, %4};"
                 :: "l"(p), "f"(a), "f"(b), "f"(c), "f"(d) : "memory");
}

// ---------------- small kernels ----------------
__global__ void zero2_kernel(float* __restrict__ a, int na, float* __restrict__ b, int nb) {
    int i = blockIdx.x * blockDim.x + threadIdx.x;
    if (i < na) { a[i] = 0.0f; return; }
    i -= na;
    if (i < nb) b[i] = 0.0f;
}

__global__ void gather_h2(const float* __restrict__ semb, const float* __restrict__ temb,
                          const int* __restrict__ sid, const int* __restrict__ tid) {
    int i = blockIdx.x * blockDim.x + threadIdx.x;
    if (i < N_SRC * HDIM) {
        int row = i >> 6, d = i & 63;
        g_xsh[i] = __float2half_rn(semb[(size_t)sid[row] * HDIM + d]);
    } else if (i < (N_SRC + N_TGT) * HDIM) {
        int j = i - N_SRC * HDIM;
        int row = j >> 6, d = j & 63;
        g_xth[j] = __float2half_rn(temb[(size_t)tid[row] * HDIM + d]);
    }
}

__global__ void relu_h2() {
    int i = blockIdx.x * blockDim.x + threadIdx.x;
    if (i < N_SRC * HDIM) {
        g_xsh[i] = __float2half_rn(fmaxf(g_xs_b[i], 0.0f));
    } else if (i < (N_SRC + N_TGT) * HDIM) {
        int j = i - N_SRC * HDIM;
        g_xth[j] = __float2half_rn(fmaxf(g_xt_b[j], 0.0f));
    }
}

__global__ void split_w(const float* __restrict__ Wq, const float* __restrict__ Wk,
                        const float* __restrict__ Wv, const float* __restrict__ Ws) {
    int i = blockIdx.x * blockDim.x + threadIdx.x;
    if (i >= 4 * WSECT) return;
    int le = i / WSECT, rem = i % WSECT;
    int n = rem >> 6, k = rem & 63;
    float v;
    if (n < 256)      v = Wq[(size_t)le * 64 * 256 + k * 256 + n];
    else if (n < 512) v = Wk[(size_t)le * 64 * 256 + k * 256 + (n - 256)];
    else if (n < 768) v = Wv[(size_t)le * 64 * 256 + k * 256 + (n - 512)];
    else              v = Ws[(size_t)le * 64 * 64 + k * 64 + (n - 768)];
    split2h(v, g_wth[i], g_wtl[i]);
}

// ---------------- tensor-core projection GEMM, permuted-B vector epilogue (R16) ------
__global__ void __launch_bounds__(256) proj_mma(
    const __half* __restrict__ Xh, int N,
    int off0, int off1, int off2, int off3,
    const float* __restrict__ b0, const float* __restrict__ b1,
    const float* __restrict__ b2, const float* __restrict__ b3,
    __half* __restrict__ o0, __half* __restrict__ o1,
    __half* __restrict__ o2, float* __restrict__ o3) {
    extern __shared__ __half sm[];
    __half* Ah = sm;                           // [128][PADK]
    __half* Bh = Ah + 128 * PADK;              // [64][PADK]
    __half* Bl = Bh + 64 * PADK;

    int sec = blockIdx.y;                      // 0..3
    int woff_base, ncb; const float* bias; __half* outh = 0; float* outf = 0;
    if (sec == 0)      { woff_base = off0; bias = b0; outh = o0; ncb = 4; }
    else if (sec == 1) { woff_base = off1; bias = b1; outh = o1; ncb = 4; }
    else if (sec == 2) { woff_base = off2; bias = b2; outh = o2; ncb = 4; }
    else               { woff_base = off3; bias = b3; outf = o3; ncb = 1; }

    int t = threadIdx.x;
    int rowbase = blockIdx.x * 128;

    const uint4* xh4 = (const uint4*)Xh;
    uint4 z4 = make_uint4(0u, 0u, 0u, 0u);
    #pragma unroll
    for (int i = 0; i < 4; i++) {
        int idx = t + i * 256;
        int r = idx >> 3, c = idx & 7;
        int gr = rowbase + r;
        uint4 vh = z4;
        if (gr < N) vh = xh4[(size_t)gr * 8 + c];
        *(uint4*)(Ah + r * PADK + c * 8) = vh;
    }

    int lane = t & 31, warp = t >> 5;
    int wr = warp >> 1, wc = warp & 1;
    int lrow = lane & 7, lsel = lane >> 3;
    int q4 = lane & 3;
    unsigned ah_u = su32(Ah), bh_u = su32(Bh), bl_u = su32(Bl);

    for (int lcb = 0; lcb < ncb; lcb++) {
        if (lcb) __syncthreads();
        int woff = woff_base + lcb * 64 * 64;
        const uint4* wh4 = (const uint4*)(g_wth + woff);
        const uint4* wl4 = (const uint4*)(g_wtl + woff);
        #pragma unroll
        for (int i = 0; i < 2; i++) {
            int idx = t + i * 256;
            int p = idx >> 3, c = idx & 7;
            // field-swap permutation within each 32-col warp tile
            int wcp = p >> 5, inner = p & 31;
            int nlog = wcp * 32 + ((inner >> 1) & 3) * 8 + (inner >> 3) * 2 + (inner & 1);
            *(uint4*)(Bh + p * PADK + c * 8) = wh4[nlog * 8 + c];
            *(uint4*)(Bl + p * PADK + c * 8) = wl4[nlog * 8 + c];
        }
        __syncthreads();

        float acc[2][4][4];
        #pragma unroll
        for (int mt = 0; mt < 2; mt++)
            #pragma unroll
            for (int nt = 0; nt < 4; nt++)
                #pragma unroll
                for (int r = 0; r < 4; r++) acc[mt][nt][r] = 0.0f;

        #pragma unroll
        for (int kc = 0; kc < 4; kc++) {
            int k0 = kc * 16;
            unsigned ah[2][4], bh[2][4], bl[2][4];
            #pragma unroll
            for (int mt = 0; mt < 2; mt++) {
                int row = wr * 32 + mt * 16 + (lsel & 1) * 8 + lrow;
                int koff = k0 + (lsel >> 1) * 8;
                unsigned boff = (unsigned)(row * PADK + koff) * 2u;
                ldsm4(ah[mt][0], ah[mt][1], ah[mt][2], ah[mt][3], ah_u + boff);
            }
            #pragma unroll
            for (int nt2 = 0; nt2 < 2; nt2++) {
                int n = wc * 32 + nt2 * 16 + (lsel >> 1) * 8 + lrow;
                int koff = k0 + (lsel & 1) * 8;
                unsigned boff = (unsigned)(n * PADK + koff) * 2u;
                ldsm4(bh[nt2][0], bh[nt2][1], bh[nt2][2], bh[nt2][3], bh_u + boff);
                ldsm4(bl[nt2][0], bl[nt2][1], bl[nt2][2], bl[nt2][3], bl_u + boff);
            }
            #pragma unroll
            for (int mt = 0; mt < 2; mt++)
                #pragma unroll
                for (int nt = 0; nt < 4; nt++) {
                    int g = nt >> 1, hf = (nt & 1) * 2;
                    mma16816h(acc[mt][nt], ah[mt], bh[g][hf], bh[g][hf + 1]);
                    mma16816h(acc[mt][nt], ah[mt], bl[g][hf], bl[g][hf + 1]);
                }
        }

        // epilogue: thread owns 8 consecutive logical cols [colb, colb+8)
        int colb = lcb * 64 + wc * 32 + q4 * 8;
        float4 bv0 = *(const float4*)(bias + colb);
        float4 bv1 = *(const float4*)(bias + colb + 4);
        #pragma unroll
        for (int mt = 0; mt < 2; mt++) {
            int ra = rowbase + wr * 32 + mt * 16 + (lane >> 2);
            int rb = ra + 8;
            if (sec < 3) {
                uint4 sa, sb;
                __half2* pa = (__half2*)&sa;
                __half2* pb = (__half2*)&sb;
                pa[0] = __floats2half2_rn(acc[mt][0][0] + bv0.x, acc[mt][0][1] + bv0.y);
                pa[1] = __floats2half2_rn(acc[mt][1][0] + bv0.z, acc[mt][1][1] + bv0.w);
                pa[2] = __floats2half2_rn(acc[mt][2][0] + bv1.x, acc[mt][2][1] + bv1.y);
                pa[3] = __floats2half2_rn(acc[mt][3][0] + bv1.z, acc[mt][3][1] + bv1.w);
                pb[0] = __floats2half2_rn(acc[mt][0][2] + bv0.x, acc[mt][0][3] + bv0.y);
                pb[1] = __floats2half2_rn(acc[mt][1][2] + bv0.z, acc[mt][1][3] + bv0.w);
                pb[2] = __floats2half2_rn(acc[mt][2][2] + bv1.x, acc[mt][2][3] + bv1.y);
                pb[3] = __floats2half2_rn(acc[mt][3][2] + bv1.z, acc[mt][3][3] + bv1.w);
                if (ra < N) *(uint4*)(outh + (size_t)ra * 256 + colb) = sa;
                if (rb < N) *(uint4*)(outh + (size_t)rb * 256 + colb) = sb;
            } else {
                float4 fa0 = make_float4(acc[mt][0][0] + bv0.x, acc[mt][0][1] + bv0.y,
                                         acc[mt][1][0] + bv0.z, acc[mt][1][1] + bv0.w);
                float4 fa1 = make_float4(acc[mt][2][0] + bv1.x, acc[mt][2][1] + bv1.y,
                                         acc[mt][3][0] + bv1.z, acc[mt][3][1] + bv1.w);
                float4 fb0 = make_float4(acc[mt][0][2] + bv0.x, acc[mt][0][3] + bv0.y,
                                         acc[mt][1][2] + bv0.z, acc[mt][1][3] + bv0.w);
                float4 fb1 = make_float4(acc[mt][2][2] + bv1.x, acc[mt][2][3] + bv1.y,
                                         acc[mt][3][2] + bv1.z, acc[mt][3][3] + bv1.w);
                if (ra < N) {
                    *(float4*)(outf + (size_t)ra * 64 + colb) = fa0;
                    *(float4*)(outf + (size_t)ra * 64 + colb + 4) = fa1;
                }
                if (rb < N) {
                    *(float4*)(outf + (size_t)rb * 64 + colb) = fb0;
                    *(float4*)(outf + (size_t)rb * 64 + colb + 4) = fb1;
                }
            }
        }
    }
}

// ---------------- score+exp+denom: 2 edges per warp, 16 lanes per edge ----------------
__global__ void scoreexp_kernel(const int* __restrict__ esrc, const int* __restrict__ edst,
                                const __half* __restrict__ q, const __half* __restrict__ k,
                                float* __restrict__ score, float* __restrict__ denom,
                                int nedge) {
    int gw = (blockIdx.x * blockDim.x + threadIdx.x) >> 5;
    int lane = threadIdx.x & 31;
    int e = gw * 2 + (lane >> 4);
    if (e >= nedge) return;
    int li = lane & 15;
    int h = li >> 2, sub = li & 3;             // 4 lanes per head, 16 halves each

    int s = esrc[e], d = edst[e];
    const __half* qb = q + (size_t)d * QKDIM + h * HDIM + sub * 16;
    const __half* kb = k + (size_t)s * QKDIM + h * HDIM + sub * 16;
    uint4 qa0 = *(const uint4*)(qb);
    uint4 qa1 = *(const uint4*)(qb + 8);
    uint4 ka0 = *(const uint4*)(kb);
    uint4 ka1 = *(const uint4*)(kb + 8);
    float dot = dot8h(qa0, ka0) + dot8h(qa1, ka1);
    dot += __shfl_down_sync(0xffffffffu, dot, 2, 4);
    dot += __shfl_down_sync(0xffffffffu, dot, 1, 4);
    if (sub == 0) {
        float ex = __expf(dot * 0.125f);
        score[(size_t)e * NHEADS + h] = ex;
        atomicAdd(&denom[(size_t)d * NHEADS + h], ex);
    }
}

// ---------------- aggregation: 2 edges per warp, v4 vector atomics (R14) ----------
__global__ void agg_kernel(const int* __restrict__ esrc, const int* __restrict__ edst,
                           const float* __restrict__ sc, const float* __restrict__ den,
                           const __half* __restrict__ v, float* __restrict__ out, int nedge) {
    int gw = (blockIdx.x * blockDim.x + threadIdx.x) >> 5;
    int lane = threadIdx.x & 31;
    int e = gw * 2 + (lane >> 4);
    if (e >= nedge) return;
    int li = lane & 15;                        // output floats [li*4, li*4+4)

    int s = esrc[e], d = edst[e];
    float4 scv = *(const float4*)(sc + (size_t)e * NHEADS);
    float4 dnv = *(const float4*)(den + (size_t)d * NHEADS);
    float a0 = 0.25f * scv.x / dnv.x;
    float a1 = 0.25f * scv.y / dnv.y;
    float a2 = 0.25f * scv.z / dnv.z;
    float a3 = 0.25f * scv.w / dnv.w;

    const __half* vb = v + (size_t)s * QKDIM + li * 4;
    uint2 r0 = *(const uint2*)(vb);
    uint2 r1 = *(const uint2*)(vb + 64);
    uint2 r2 = *(const uint2*)(vb + 128);
    uint2 r3 = *(const uint2*)(vb + 192);
    const __half2* h0 = (const __half2*)&r0;
    const __half2* h1 = (const __half2*)&r1;
    const __half2* h2 = (const __half2*)&r2;
    const __half2* h3 = (const __half2*)&r3;
    float2 v0a = __half22float2(h0[0]), v0b = __half22float2(h0[1]);
    float2 v1a = __half22float2(h1[0]), v1b = __half22float2(h1[1]);
    float2 v2a = __half22float2(h2[0]), v2b = __half22float2(h2[1]);
    float2 v3a = __half22float2(h3[0]), v3b = __half22float2(h3[1]);

    float o0 = a0 * v0a.x + a1 * v1a.x + a2 * v2a.x + a3 * v3a.x;
    float o1 = a0 * v0a.y + a1 * v1a.y + a2 * v2a.y + a3 * v3a.y;
    float o2 = a0 * v0b.x + a1 * v1b.x + a2 * v2b.x + a3 * v3b.x;
    float o3 = a0 * v0b.y + a1 * v1b.y + a2 * v2b.y + a3 * v3b.y;

    red_add_v4(out + (size_t)d * HDIM + li * 4, o0, o1, o2, o3);
}

// ---------------- classifier ----------------
__global__ void pred_kernel(const int* __restrict__ l0, const int* __restrict__ l1,
                            const float* __restrict__ xs, const float* __restrict__ xt,
                            float* __restrict__ out, int n) {
    int gid = blockIdx.x * blockDim.x + threadIdx.x;
    int pair = gid >> 3, sub = gid & 7;
    if (pair >= n) return;
    int a = l0[pair], b = l1[pair];
    const float4* xa = (const float4*)(xs + (size_t)a * HDIM);
    const float4* xb = (const float4*)(xt + (size_t)b * HDIM);
    float4 p0 = xa[sub * 2], p1 = xa[sub * 2 + 1];
    float4 q0 = xb[sub * 2], q1 = xb[sub * 2 + 1];
    float dot = p0.x * q0.x + p0.y * q0.y + p0.z * q0.z + p0.w * q0.w
              + p1.x * q1.x + p1.y * q1.y + p1.z * q1.z + p1.w * q1.w;
    dot += __shfl_down_sync(0xffffffffu, dot, 4, 8);
    dot += __shfl_down_sync(0xffffffffu, dot, 2, 8);
    dot += __shfl_down_sync(0xffffffffu, dot, 1, 8);
    if (sub == 0) out[pair] = dot;
}

// ---------------- launch ----------------
extern "C" void kernel_launch(void* const* d_in, const int* in_sizes, int n_in,
                              void* d_out, int out_size) {
    const float* src_emb = (const float*)d_in[0];
    const float* tgt_emb = (const float*)d_in[1];
    const float* Wq = (const float*)d_in[2];
    const float* bq = (const float*)d_in[3];
    const float* Wk = (const float*)d_in[4];
    const float* bk = (const float*)d_in[5];
    const float* Wv = (const float*)d_in[6];
    const float* bv = (const float*)d_in[7];
    const float* Ws = (const float*)d_in[8];
    const float* bs = (const float*)d_in[9];
    const int* nid_s = (const int*)d_in[10];
    const int* nid_t = (const int*)d_in[11];
    const int* e_st  = (const int*)d_in[12];
    const int* e_ts  = (const int*)d_in[13];
    const int* lbl   = (const int*)d_in[14];
    float* out = (float*)d_out;

    float *xs_a, *xs_b, *xt_a, *xt_b, *sc_st, *sc_ts, *d_st, *d_ts;
    __half *q_st, *k_ts, *v_ts, *q_ts, *k_st, *v_st, *xsh, *xth;
    cudaGetSymbolAddress((void**)&xs_a, g_xs_a);
    cudaGetSymbolAddress((void**)&xs_b, g_xs_b);
    cudaGetSymbolAddress((void**)&xt_a, g_xt_a);
    cudaGetSymbolAddress((void**)&xt_b, g_xt_b);
    cudaGetSymbolAddress((void**)&q_st, g_q_st);
    cudaGetSymbolAddress((void**)&k_ts, g_k_ts);
    cudaGetSymbolAddress((void**)&v_ts, g_v_ts);
    cudaGetSymbolAddress((void**)&q_ts, g_q_ts);
    cudaGetSymbolAddress((void**)&k_st, g_k_st);
    cudaGetSymbolAddress((void**)&v_st, g_v_st);
    cudaGetSymbolAddress((void**)&sc_st, g_sc_st);
    cudaGetSymbolAddress((void**)&sc_ts, g_sc_ts);
    cudaGetSymbolAddress((void**)&d_st, g_d_st);
    cudaGetSymbolAddress((void**)&d_ts, g_d_ts);
    cudaGetSymbolAddress((void**)&xsh, g_xsh);
    cudaGetSymbolAddress((void**)&xth, g_xth);

    const int SMEM = (128 * PADK + 64 * PADK * 2) * 2;  // 36864 B
    cudaFuncSetAttribute(proj_mma, cudaFuncAttributeMaxDynamicSharedMemorySize, SMEM);

    int nz0 = (N_TGT + N_SRC) * NHEADS;
    int nx = (N_SRC + N_TGT) * HDIM;
    zero2_kernel<<<(nz0 + 255) / 256, 256>>>(d_st, N_TGT * NHEADS, d_ts, N_SRC * NHEADS);
    gather_h2<<<(nx + 255) / 256, 256>>>(src_emb, tgt_emb, nid_s, nid_t);
    split_w<<<(4 * WSECT + 255) / 256, 256>>>(Wq, Wk, Wv, Ws);

    int sb2 = (((N_E + 1) / 2) * 32 + 255) / 256;  // two edges per warp (scoreexp, agg)

    for (int l = 0; l < 2; l++) {
        float* out_s = l ? xs_a : xs_b;
        float* out_t = l ? xt_a : xt_b;
        if (l) {
            relu_h2<<<(nx + 255) / 256, 256>>>();
            zero2_kernel<<<(nz0 + 255) / 256, 256>>>(d_st, N_TGT * NHEADS, d_ts, N_SRC * NHEADS);
        }

        int le0 = l * 2 + 0, le1 = l * 2 + 1;
        dim3 gs((N_SRC + 127) / 128, 4), gt((N_TGT + 127) / 128, 4);
        // src-side: k_st(Wk l,0), v_st(Wv l,0), q_ts(Wq l,1), skip(Ws l,1)
        proj_mma<<<gs, 256, SMEM>>>(xsh, N_SRC,
            le0 * WSECT + 256 * 64, le0 * WSECT + 512 * 64,
            le1 * WSECT + 0,        le1 * WSECT + 768 * 64,
            bk + le0 * 256, bv + le0 * 256, bq + le1 * 256, bs + le1 * 64,
            k_st, v_st, q_ts, out_s);
        // tgt-side: q_st(Wq l,0), k_ts(Wk l,1), v_ts(Wv l,1), skip(Ws l,0)
        proj_mma<<<gt, 256, SMEM>>>(xth, N_TGT,
            le0 * WSECT + 0,        le1 * WSECT + 256 * 64,
            le1 * WSECT + 512 * 64, le0 * WSECT + 768 * 64,
            bq + le0 * 256, bk + le1 * 256, bv + le1 * 256, bs + le0 * 64,
            q_st, k_ts, v_ts, out_t);

        scoreexp_kernel<<<sb2, 256>>>(e_st, e_st + N_E, q_st, k_st, sc_st, d_st, N_E);
        scoreexp_kernel<<<sb2, 256>>>(e_ts, e_ts + N_E, q_ts, k_ts, sc_ts, d_ts, N_E);

        agg_kernel<<<sb2, 256>>>(e_st, e_st + N_E, sc_st, d_st, v_st, out_t, N_E);
        agg_kernel<<<sb2, 256>>>(e_ts, e_ts + N_E, sc_ts, d_ts, v_ts, out_s, N_E);
    }

    pred_kernel<<<(N_LBL * 8 + 255) / 256, 256>>>(lbl, lbl + N_LBL, xs_a, xt_a, out, N_LBL);
}